// round 8
// baseline (speedup 1.0000x reference)
#include <cuda_runtime.h>
#include <cstdint>

#define T_ 256
#define D_ 64
#define H_ 256
#define B_ 512
#define ROWSC 8          // batch rows per cluster
#define JH 128           // output columns per CTA
#define NCTA 128
#define THREADS 512      // (pg:1) | (j0:7) | (kh:1)

#define VS 264           // padded row stride for H-vectors (bank shift 8)
#define XS 68            // padded row stride for x (bank shift 4)
#define PS 129           // padded PART stride

// packed: P[k4 * O + o] = float4{ W[o][4k4+0..3] }
__device__ float4 g_w1p[(H_ / 4) * H_];
__device__ float4 g_w2p[(H_ / 4) * H_];
__device__ float4 g_whhp[(H_ / 4) * (3 * H_)];
__device__ float4 g_wihp[(D_ / 4) * (3 * H_)];
__device__ float4 g_woutp[(H_ / 4) * H_];
__device__ float g_dt[T_];

#define N_W1 ((H_ / 4) * H_)
#define N_WHH ((H_ / 4) * (3 * H_))
#define N_WIH ((D_ / 4) * (3 * H_))
#define PK_TOTAL (3 * N_W1 + N_WHH + N_WIH)

__global__ void pack_all_kernel(const float* __restrict__ w1,
                                const float* __restrict__ w2,
                                const float* __restrict__ whh,
                                const float* __restrict__ wih,
                                const float* __restrict__ wout,
                                const float* __restrict__ tps) {
    int idx = blockIdx.x * blockDim.x + threadIdx.x;
    if (idx < T_) {
        g_dt[idx] = (idx == 0) ? (tps[0] - (tps[0] - 0.01f))
                               : (tps[idx] - tps[idx - 1]);
    }
    if (idx >= PK_TOTAL) return;
    const float* src; float4* dst; int O, K, local = idx;
    if (local < N_W1) { src = w1; dst = g_w1p; O = H_; K = H_; }
    else if ((local -= N_W1) < N_W1) { src = w2; dst = g_w2p; O = H_; K = H_; }
    else if ((local -= N_W1) < N_WHH) { src = whh; dst = g_whhp; O = 3 * H_; K = H_; }
    else if ((local -= N_WHH) < N_WIH) { src = wih; dst = g_wihp; O = 3 * H_; K = D_; }
    else { local -= N_WIH; src = wout; dst = g_woutp; O = H_; K = H_; }
    int k4 = local / O;
    int o = local % O;
    const float* s = src + (size_t)o * K + 4 * k4;
    dst[local] = make_float4(s[0], s[1], s[2], s[3]);
}

typedef unsigned long long ull;
__device__ __forceinline__ ull ffma2(ull a, ull b, ull c) {
    ull d; asm("fma.rn.f32x2 %0, %1, %2, %3;" : "=l"(d) : "l"(a), "l"(b), "l"(c)); return d;
}
__device__ __forceinline__ float hadd2(ull v) {
    float2 f; asm("mov.b64 {%0, %1}, %2;" : "=f"(f.x), "=f"(f.y) : "l"(v));
    return f.x + f.y;
}
__device__ __forceinline__ float sigmoidf_(float v) { return 1.0f / (1.0f + expf(-v)); }

__device__ __forceinline__ void sts_peer_f32(const void* laddr, uint32_t peer, float v) {
    uint32_t la = (uint32_t)__cvta_generic_to_shared(laddr), ra;
    asm("mapa.shared::cluster.u32 %0, %1, %2;" : "=r"(ra) : "r"(la), "r"(peer));
    asm volatile("st.shared::cluster.b32 [%0], %1;" :: "r"(ra), "r"(__float_as_uint(v)) : "memory");
}
__device__ __forceinline__ void cluster_sync_() {
    asm volatile("barrier.cluster.arrive.aligned;" ::: "memory");
    asm volatile("barrier.cluster.wait.aligned;" ::: "memory");
}

// single-matrix GEMM, 4 rows, nkk quads; wp pre-offset to (kb, col); v* pre-offset to kb
__device__ __forceinline__ void gemm4p(ull acc[4], const ulonglong2* __restrict__ wp, int wstep,
                                       const ulonglong2* __restrict__ v0,
                                       const ulonglong2* __restrict__ v1,
                                       const ulonglong2* __restrict__ v2,
                                       const ulonglong2* __restrict__ v3,
                                       int nkk) {
#pragma unroll 8
    for (int kk = 0; kk < nkk; kk++) {
        ulonglong2 w = wp[kk * wstep];
        ulonglong2 a0 = v0[kk], a1 = v1[kk], a2 = v2[kk], a3 = v3[kk];
        acc[0] = ffma2(w.x, a0.x, acc[0]); acc[0] = ffma2(w.y, a0.y, acc[0]);
        acc[1] = ffma2(w.x, a1.x, acc[1]); acc[1] = ffma2(w.y, a1.y, acc[1]);
        acc[2] = ffma2(w.x, a2.x, acc[2]); acc[2] = ffma2(w.y, a2.y, acc[2]);
        acc[3] = ffma2(w.x, a3.x, acc[3]); acc[3] = ffma2(w.y, a3.y, acc[3]);
    }
}

#define PART(slot, j) spart[(slot) * PS + (j)]

__global__ void __launch_bounds__(THREADS, 1) __cluster_dims__(2, 1, 1)
gruode_kernel(const float* __restrict__ x,
              const float* __restrict__ mask,
              const float* __restrict__ b_ih,
              const float* __restrict__ b_hh,
              const float* __restrict__ b1,
              const float* __restrict__ b2,
              const float* __restrict__ b_out,
              float* __restrict__ out) {
    __shared__ __align__(16) float hbuf[ROWSC][VS];
    __shared__ __align__(16) float odebuf[ROWSC][VS];
    __shared__ __align__(16) float a1buf[ROWSC][VS];
    __shared__ __align__(16) float xbuf[ROWSC][XS];
    __shared__ float smk[ROWSC];
    __shared__ float spart[32 * PS];

    const ulonglong2* w1u = reinterpret_cast<const ulonglong2*>(g_w1p);
    const ulonglong2* w2u = reinterpret_cast<const ulonglong2*>(g_w2p);
    const ulonglong2* whhu = reinterpret_cast<const ulonglong2*>(g_whhp);
    const ulonglong2* wihu = reinterpret_cast<const ulonglong2*>(g_wihp);
    const ulonglong2* woutu = reinterpret_cast<const ulonglong2*>(g_woutp);

    const int tid = threadIdx.x;
    const int pg = tid & 1;            // row group: rows 4*pg..4*pg+3 (lane bit 0!)
    const int j0 = (tid >> 1) & (JH - 1);
    const int kh = (tid >> 8) & 1;     // k-half
    const int rbase = 4 * pg;
    uint32_t rank;
    asm("mov.u32 %0, %%cluster_ctarank;" : "=r"(rank));
    const uint32_t peer = rank ^ 1u;
    const int jg = (int)rank * JH + j0;
    const int row0 = (blockIdx.x >> 1) * ROWSC;
    const int kb = kh * 32;            // quad base for H-dim GEMMs
    const int kbx = kh * 8;            // quad base for D-dim GEMM
    const bool comb = (kh == 0);

    for (int idx = tid; idx < ROWSC * VS; idx += THREADS) (&hbuf[0][0])[idx] = 0.0f;

    float hcur[4], hlast[4], seen[4], hode[4];
#pragma unroll
    for (int r = 0; r < 4; r++) { hcur[r] = 0.0f; hlast[r] = 0.0f; seen[r] = 0.0f; hode[r] = 0.0f; }

    const float b1j = b1[jg];
    const float b2j = b2[jg];
    const float brz_r = b_ih[jg] + b_hh[jg];
    const float brz_z = b_ih[H_ + jg] + b_hh[H_ + jg];
    const float bin_ = b_ih[2 * H_ + jg];
    const float bhn = b_hh[2 * H_ + jg];

    // hoisted weight bases (pre-offset by k-half and column)
    const ulonglong2* w1p = w1u + kb * H_ + jg;
    const ulonglong2* w2p = w2u + kb * H_ + jg;
    const ulonglong2* whp = whhu + kb * (3 * H_) + jg;          // r row; +H_ => z; +2H_ => n
    const ulonglong2* wip = wihu + kbx * (3 * H_) + jg;
    const ulonglong2* wop = woutu + kb * H_ + jg;

    cluster_sync_();

    for (int t = 0; t < T_; t++) {
        // ---- stage 1: x_t + mask ----
        {
            int r = tid >> 6, c = tid & 63;
            xbuf[r][c] = x[((size_t)(row0 + r) * T_ + t) * D_ + c];
        }
        if (tid < ROWSC) smk[tid] = mask[(size_t)(row0 + tid) * T_ + t];

        // ---- stage 2: a1 = tanh(h @ w1^T + b1) ----
        {
            ull acc[4] = {0ull, 0ull, 0ull, 0ull};
            gemm4p(acc, w1p, H_,
                   (const ulonglong2*)&hbuf[rbase + 0][4 * kb],
                   (const ulonglong2*)&hbuf[rbase + 1][4 * kb],
                   (const ulonglong2*)&hbuf[rbase + 2][4 * kb],
                   (const ulonglong2*)&hbuf[rbase + 3][4 * kb], 32);
            float hs[4];
#pragma unroll
            for (int rr = 0; rr < 4; rr++) hs[rr] = hadd2(acc[rr]);
            if (!comb) {
#pragma unroll
                for (int rr = 0; rr < 4; rr++) PART(rbase + rr, j0) = hs[rr];
            }
            __syncthreads();
            if (comb) {
#pragma unroll
                for (int rr = 0; rr < 4; rr++) {
                    int r = rbase + rr;
                    float a = tanhf(b1j + hs[rr] + PART(r, j0));
                    a1buf[r][jg] = a;
                    sts_peer_f32(&a1buf[r][jg], peer, a);
                }
            }
        }
        cluster_sync_();

        // ---- stage 3: f = a1 @ w2^T + b2 ; euler ; h_ode ----
        {
            ull acc[4] = {0ull, 0ull, 0ull, 0ull};
            gemm4p(acc, w2p, H_,
                   (const ulonglong2*)&a1buf[rbase + 0][4 * kb],
                   (const ulonglong2*)&a1buf[rbase + 1][4 * kb],
                   (const ulonglong2*)&a1buf[rbase + 2][4 * kb],
                   (const ulonglong2*)&a1buf[rbase + 3][4 * kb], 32);
            float hs[4];
#pragma unroll
            for (int rr = 0; rr < 4; rr++) hs[rr] = hadd2(acc[rr]);
            if (!comb) {
#pragma unroll
                for (int rr = 0; rr < 4; rr++) PART(rbase + rr, j0) = hs[rr];
            }
            __syncthreads();
            if (comb) {
                const float dtv = g_dt[t];
#pragma unroll
                for (int rr = 0; rr < 4; rr++) {
                    int r = rbase + rr;
                    float f = b2j + hs[rr] + PART(r, j0);
                    float he = hcur[rr] + dtv * f;
                    float ho = (seen[rr] > 0.0f) ? he : hcur[rr];
                    hode[rr] = ho;
                    odebuf[r][jg] = ho;
                    sts_peer_f32(&odebuf[r][jg], peer, ho);
                }
            }
        }
        cluster_sync_();

        // ---- stage 4: gates, fully fused k-loops ----
        {
            ull aR[4] = {0ull, 0ull, 0ull, 0ull};
            ull aZ[4] = {0ull, 0ull, 0ull, 0ull};
            ull aN[4] = {0ull, 0ull, 0ull, 0ull};
            ull aI[4] = {0ull, 0ull, 0ull, 0ull};

            // recurrent part: r,z,n over odebuf (one LDS per quad per row)
            {
                const ulonglong2* v0 = (const ulonglong2*)&odebuf[rbase + 0][4 * kb];
                const ulonglong2* v1 = (const ulonglong2*)&odebuf[rbase + 1][4 * kb];
                const ulonglong2* v2 = (const ulonglong2*)&odebuf[rbase + 2][4 * kb];
                const ulonglong2* v3 = (const ulonglong2*)&odebuf[rbase + 3][4 * kb];
#pragma unroll 4
                for (int kk = 0; kk < 32; kk++) {
                    ulonglong2 wr = whp[kk * (3 * H_)];
                    ulonglong2 wz = whp[kk * (3 * H_) + H_];
                    ulonglong2 wn = whp[kk * (3 * H_) + 2 * H_];
                    ulonglong2 a0 = v0[kk], a1v = v1[kk], a2 = v2[kk], a3 = v3[kk];
                    aR[0] = ffma2(wr.x, a0.x, aR[0]); aR[0] = ffma2(wr.y, a0.y, aR[0]);
                    aZ[0] = ffma2(wz.x, a0.x, aZ[0]); aZ[0] = ffma2(wz.y, a0.y, aZ[0]);
                    aN[0] = ffma2(wn.x, a0.x, aN[0]); aN[0] = ffma2(wn.y, a0.y, aN[0]);
                    aR[1] = ffma2(wr.x, a1v.x, aR[1]); aR[1] = ffma2(wr.y, a1v.y, aR[1]);
                    aZ[1] = ffma2(wz.x, a1v.x, aZ[1]); aZ[1] = ffma2(wz.y, a1v.y, aZ[1]);
                    aN[1] = ffma2(wn.x, a1v.x, aN[1]); aN[1] = ffma2(wn.y, a1v.y, aN[1]);
                    aR[2] = ffma2(wr.x, a2.x, aR[2]); aR[2] = ffma2(wr.y, a2.y, aR[2]);
                    aZ[2] = ffma2(wz.x, a2.x, aZ[2]); aZ[2] = ffma2(wz.y, a2.y, aZ[2]);
                    aN[2] = ffma2(wn.x, a2.x, aN[2]); aN[2] = ffma2(wn.y, a2.y, aN[2]);
                    aR[3] = ffma2(wr.x, a3.x, aR[3]); aR[3] = ffma2(wr.y, a3.y, aR[3]);
                    aZ[3] = ffma2(wz.x, a3.x, aZ[3]); aZ[3] = ffma2(wz.y, a3.y, aZ[3]);
                    aN[3] = ffma2(wn.x, a3.x, aN[3]); aN[3] = ffma2(wn.y, a3.y, aN[3]);
                }
            }
            // input part: r,z,i over xbuf
            {
                const ulonglong2* v0 = (const ulonglong2*)&xbuf[rbase + 0][4 * kbx];
                const ulonglong2* v1 = (const ulonglong2*)&xbuf[rbase + 1][4 * kbx];
                const ulonglong2* v2 = (const ulonglong2*)&xbuf[rbase + 2][4 * kbx];
                const ulonglong2* v3 = (const ulonglong2*)&xbuf[rbase + 3][4 * kbx];
#pragma unroll
                for (int kk = 0; kk < 8; kk++) {
                    ulonglong2 wr = wip[kk * (3 * H_)];
                    ulonglong2 wz = wip[kk * (3 * H_) + H_];
                    ulonglong2 wn = wip[kk * (3 * H_) + 2 * H_];
                    ulonglong2 a0 = v0[kk], a1v = v1[kk], a2 = v2[kk], a3 = v3[kk];
                    aR[0] = ffma2(wr.x, a0.x, aR[0]); aR[0] = ffma2(wr.y, a0.y, aR[0]);
                    aZ[0] = ffma2(wz.x, a0.x, aZ[0]); aZ[0] = ffma2(wz.y, a0.y, aZ[0]);
                    aI[0] = ffma2(wn.x, a0.x, aI[0]); aI[0] = ffma2(wn.y, a0.y, aI[0]);
                    aR[1] = ffma2(wr.x, a1v.x, aR[1]); aR[1] = ffma2(wr.y, a1v.y, aR[1]);
                    aZ[1] = ffma2(wz.x, a1v.x, aZ[1]); aZ[1] = ffma2(wz.y, a1v.y, aZ[1]);
                    aI[1] = ffma2(wn.x, a1v.x, aI[1]); aI[1] = ffma2(wn.y, a1v.y, aI[1]);
                    aR[2] = ffma2(wr.x, a2.x, aR[2]); aR[2] = ffma2(wr.y, a2.y, aR[2]);
                    aZ[2] = ffma2(wz.x, a2.x, aZ[2]); aZ[2] = ffma2(wz.y, a2.y, aZ[2]);
                    aI[2] = ffma2(wn.x, a2.x, aI[2]); aI[2] = ffma2(wn.y, a2.y, aI[2]);
                    aR[3] = ffma2(wr.x, a3.x, aR[3]); aR[3] = ffma2(wr.y, a3.y, aR[3]);
                    aZ[3] = ffma2(wz.x, a3.x, aZ[3]); aZ[3] = ffma2(wz.y, a3.y, aZ[3]);
                    aI[3] = ffma2(wn.x, a3.x, aI[3]); aI[3] = ffma2(wn.y, a3.y, aI[3]);
                }
            }

            float hsR[4], hsZ[4], hsN[4], hsI[4];
#pragma unroll
            for (int rr = 0; rr < 4; rr++) {
                hsR[rr] = hadd2(aR[rr]); hsZ[rr] = hadd2(aZ[rr]);
                hsN[rr] = hadd2(aN[rr]); hsI[rr] = hadd2(aI[rr]);
            }
            if (!comb) {
#pragma unroll
                for (int rr = 0; rr < 4; rr++) {
                    int r = rbase + rr;
                    PART(r, j0) = hsR[rr];
                    PART(8 + r, j0) = hsZ[rr];
                    PART(16 + r, j0) = hsN[rr];
                    PART(24 + r, j0) = hsI[rr];
                }
            }
            __syncthreads();
            if (comb) {
#pragma unroll
                for (int rr = 0; rr < 4; rr++) {
                    int r = rbase + rr;
                    float fr = brz_r + hsR[rr] + PART(r, j0);
                    float fz = brz_z + hsZ[rr] + PART(8 + r, j0);
                    float fn = bhn + hsN[rr] + PART(16 + r, j0);
                    float fi = bin_ + hsI[rr] + PART(24 + r, j0);
                    float rg = sigmoidf_(fr);
                    float zg = sigmoidf_(fz);
                    float ng = tanhf(fi + rg * fn);
                    float hrnn = (1.0f - zg) * ng + zg * hode[rr];
                    float m = smk[r];
                    float hn = (m > 0.5f) ? hrnn : hode[rr];
                    hcur[rr] = hn;
                    hlast[rr] = (m > 0.5f) ? hn : hlast[rr];
                    seen[rr] = fmaxf(seen[rr], m);
                    hbuf[r][jg] = hn;
                    sts_peer_f32(&hbuf[r][jg], peer, hn);
                }
            }
        }
        cluster_sync_();
    }

    // ---- final projection: out = h_last @ w_out^T + b_out ----
    if (comb) {
#pragma unroll
        for (int rr = 0; rr < 4; rr++) {
            int r = rbase + rr;
            hbuf[r][jg] = hlast[rr];
            sts_peer_f32(&hbuf[r][jg], peer, hlast[rr]);
        }
    }
    cluster_sync_();
    {
        ull acc[4] = {0ull, 0ull, 0ull, 0ull};
        gemm4p(acc, wop, H_,
               (const ulonglong2*)&hbuf[rbase + 0][4 * kb],
               (const ulonglong2*)&hbuf[rbase + 1][4 * kb],
               (const ulonglong2*)&hbuf[rbase + 2][4 * kb],
               (const ulonglong2*)&hbuf[rbase + 3][4 * kb], 32);
        float hs[4];
#pragma unroll
        for (int rr = 0; rr < 4; rr++) hs[rr] = hadd2(acc[rr]);
        if (!comb) {
#pragma unroll
            for (int rr = 0; rr < 4; rr++) PART(rbase + rr, j0) = hs[rr];
        }
        __syncthreads();
        if (comb) {
            const float bo = b_out[jg];
#pragma unroll
            for (int rr = 0; rr < 4; rr++) {
                int r = rbase + rr;
                out[(size_t)(row0 + r) * H_ + jg] = bo + hs[rr] + PART(r, j0);
            }
        }
    }
    cluster_sync_();
}

extern "C" void kernel_launch(void* const* d_in, const int* in_sizes, int n_in,
                              void* d_out, int out_size) {
    const float* x     = (const float*)d_in[0];
    const float* tps   = (const float*)d_in[1];
    const float* mask  = (const float*)d_in[2];
    const float* w_ih  = (const float*)d_in[3];
    const float* w_hh  = (const float*)d_in[4];
    const float* b_ih  = (const float*)d_in[5];
    const float* b_hh  = (const float*)d_in[6];
    const float* w1    = (const float*)d_in[7];
    const float* b1    = (const float*)d_in[8];
    const float* w2    = (const float*)d_in[9];
    const float* b2    = (const float*)d_in[10];
    const float* w_out = (const float*)d_in[11];
    const float* b_out = (const float*)d_in[12];
    float* out = (float*)d_out;

    pack_all_kernel<<<(PK_TOTAL + 255) / 256, 256>>>(w1, w2, w_hh, w_ih, w_out, tps);
    gruode_kernel<<<NCTA, THREADS>>>(x, mask, b_ih, b_hh, b1, b2, b_out, out);
}

// round 9
// speedup vs baseline: 1.2923x; 1.2923x over previous
#include <cuda_runtime.h>
#include <cstdint>

#define T_ 256
#define D_ 64
#define H_ 256
#define B_ 512
#define ROWSC 8          // batch rows per cluster
#define JH 128           // output columns per CTA
#define NCTA 128
#define THREADS 512      // (kh:1) | (j0:7) | (pg:1)

#define VS 260           // padded row stride: 4*VS=1040 ≡ 16 (mod 32) -> no cross-pg bank clash
#define XS 68            // 4*XS=272 ≡ 16 (mod 32)
#define PS 129           // PART stride: 4*PS=516 ≡ 4 (mod 32)

// packed: P[k4 * O + o] = float4{ W[o][4k4+0..3] }
__device__ float4 g_w1p[(H_ / 4) * H_];
__device__ float4 g_w2p[(H_ / 4) * H_];
__device__ float4 g_whhp[(H_ / 4) * (3 * H_)];
__device__ float4 g_wihp[(D_ / 4) * (3 * H_)];
__device__ float4 g_woutp[(H_ / 4) * H_];
__device__ float g_dt[T_];

#define N_W1 ((H_ / 4) * H_)
#define N_WHH ((H_ / 4) * (3 * H_))
#define N_WIH ((D_ / 4) * (3 * H_))
#define PK_TOTAL (3 * N_W1 + N_WHH + N_WIH)

__global__ void pack_all_kernel(const float* __restrict__ w1,
                                const float* __restrict__ w2,
                                const float* __restrict__ whh,
                                const float* __restrict__ wih,
                                const float* __restrict__ wout,
                                const float* __restrict__ tps) {
    int idx = blockIdx.x * blockDim.x + threadIdx.x;
    if (idx < T_) {
        g_dt[idx] = (idx == 0) ? (tps[0] - (tps[0] - 0.01f))
                               : (tps[idx] - tps[idx - 1]);
    }
    if (idx >= PK_TOTAL) return;
    const float* src; float4* dst; int O, K, local = idx;
    if (local < N_W1) { src = w1; dst = g_w1p; O = H_; K = H_; }
    else if ((local -= N_W1) < N_W1) { src = w2; dst = g_w2p; O = H_; K = H_; }
    else if ((local -= N_W1) < N_WHH) { src = whh; dst = g_whhp; O = 3 * H_; K = H_; }
    else if ((local -= N_WHH) < N_WIH) { src = wih; dst = g_wihp; O = 3 * H_; K = D_; }
    else { local -= N_WIH; src = wout; dst = g_woutp; O = H_; K = H_; }
    int k4 = local / O;
    int o = local % O;
    const float* s = src + (size_t)o * K + 4 * k4;
    dst[local] = make_float4(s[0], s[1], s[2], s[3]);
}

typedef unsigned long long ull;
__device__ __forceinline__ ull ffma2(ull a, ull b, ull c) {
    ull d; asm("fma.rn.f32x2 %0, %1, %2, %3;" : "=l"(d) : "l"(a), "l"(b), "l"(c)); return d;
}
__device__ __forceinline__ float hadd2(ull v) {
    float2 f; asm("mov.b64 {%0, %1}, %2;" : "=f"(f.x), "=f"(f.y) : "l"(v));
    return f.x + f.y;
}
__device__ __forceinline__ float sigmoidf_(float v) { return 1.0f / (1.0f + expf(-v)); }

__device__ __forceinline__ void sts_peer_f32(const void* laddr, uint32_t peer, float v) {
    uint32_t la = (uint32_t)__cvta_generic_to_shared(laddr), ra;
    asm("mapa.shared::cluster.u32 %0, %1, %2;" : "=r"(ra) : "r"(la), "r"(peer));
    asm volatile("st.shared::cluster.b32 [%0], %1;" :: "r"(ra), "r"(__float_as_uint(v)) : "memory");
}
__device__ __forceinline__ void cluster_sync_() {
    asm volatile("barrier.cluster.arrive.aligned;" ::: "memory");
    asm volatile("barrier.cluster.wait.aligned;" ::: "memory");
}

// single-matrix GEMM, 4 rows, nkk quads; wp pre-offset to (kb, col); v* pre-offset to kb
__device__ __forceinline__ void gemm4p(ull acc[4], const ulonglong2* __restrict__ wp, int wstep,
                                       const ulonglong2* __restrict__ v0,
                                       const ulonglong2* __restrict__ v1,
                                       const ulonglong2* __restrict__ v2,
                                       const ulonglong2* __restrict__ v3,
                                       int nkk) {
#pragma unroll 8
    for (int kk = 0; kk < nkk; kk++) {
        ulonglong2 w = wp[kk * wstep];
        ulonglong2 a0 = v0[kk], a1 = v1[kk], a2 = v2[kk], a3 = v3[kk];
        acc[0] = ffma2(w.x, a0.x, acc[0]); acc[0] = ffma2(w.y, a0.y, acc[0]);
        acc[1] = ffma2(w.x, a1.x, acc[1]); acc[1] = ffma2(w.y, a1.y, acc[1]);
        acc[2] = ffma2(w.x, a2.x, acc[2]); acc[2] = ffma2(w.y, a2.y, acc[2]);
        acc[3] = ffma2(w.x, a3.x, acc[3]); acc[3] = ffma2(w.y, a3.y, acc[3]);
    }
}

#define PART(slot, j) spart[(slot) * PS + (j)]

__global__ void __launch_bounds__(THREADS, 1) __cluster_dims__(2, 1, 1)
gruode_kernel(const float* __restrict__ x,
              const float* __restrict__ mask,
              const float* __restrict__ b_ih,
              const float* __restrict__ b_hh,
              const float* __restrict__ b1,
              const float* __restrict__ b2,
              const float* __restrict__ b_out,
              float* __restrict__ out) {
    __shared__ __align__(16) float hbuf[ROWSC][VS];
    __shared__ __align__(16) float odebuf[ROWSC][VS];
    __shared__ __align__(16) float a1buf[ROWSC][VS];
    __shared__ __align__(16) float xbuf[ROWSC][XS];
    __shared__ float smk[ROWSC];
    __shared__ float spart[32 * PS];

    const ulonglong2* w1u = reinterpret_cast<const ulonglong2*>(g_w1p);
    const ulonglong2* w2u = reinterpret_cast<const ulonglong2*>(g_w2p);
    const ulonglong2* whhu = reinterpret_cast<const ulonglong2*>(g_whhp);
    const ulonglong2* wihu = reinterpret_cast<const ulonglong2*>(g_wihp);
    const ulonglong2* woutu = reinterpret_cast<const ulonglong2*>(g_woutp);

    const int tid = threadIdx.x;
    const int pg = tid & 1;            // row group: rows 4*pg..4*pg+3 (lane bit 0 -> LDG line dedup)
    const int j0 = (tid >> 1) & (JH - 1);
    const int kh = (tid >> 8) & 1;     // k-half
    const int rbase = 4 * pg;
    uint32_t rank;
    asm("mov.u32 %0, %%cluster_ctarank;" : "=r"(rank));
    const uint32_t peer = rank ^ 1u;
    const int jg = (int)rank * JH + j0;
    const int row0 = (blockIdx.x >> 1) * ROWSC;
    const int kb = kh * 32;            // quad base for H-dim GEMMs
    const int kbx = kh * 8;            // quad base for D-dim GEMM
    const bool comb = (kh == 0);

    for (int idx = tid; idx < ROWSC * VS; idx += THREADS) (&hbuf[0][0])[idx] = 0.0f;

    float hcur[4], hlast[4], seen[4], hode[4];
#pragma unroll
    for (int r = 0; r < 4; r++) { hcur[r] = 0.0f; hlast[r] = 0.0f; seen[r] = 0.0f; hode[r] = 0.0f; }

    const float b1j = b1[jg];
    const float b2j = b2[jg];
    const float brz_r = b_ih[jg] + b_hh[jg];
    const float brz_z = b_ih[H_ + jg] + b_hh[H_ + jg];
    const float bin_ = b_ih[2 * H_ + jg];
    const float bhn = b_hh[2 * H_ + jg];

    // hoisted weight bases (pre-offset by k-half and column)
    const ulonglong2* w1p = w1u + kb * H_ + jg;
    const ulonglong2* w2p = w2u + kb * H_ + jg;
    const ulonglong2* whp = whhu + kb * (3 * H_) + jg;          // r row; +H_ => z; +2H_ => n
    const ulonglong2* wip = wihu + kbx * (3 * H_) + jg;
    const ulonglong2* wop = woutu + kb * H_ + jg;

    cluster_sync_();

    for (int t = 0; t < T_; t++) {
        // ---- stage 1: x_t + mask ----
        {
            int r = tid >> 6, c = tid & 63;
            xbuf[r][c] = x[((size_t)(row0 + r) * T_ + t) * D_ + c];
        }
        if (tid < ROWSC) smk[tid] = mask[(size_t)(row0 + tid) * T_ + t];

        // ---- stage 2: a1 = tanh(h @ w1^T + b1) ----
        {
            ull acc[4] = {0ull, 0ull, 0ull, 0ull};
            gemm4p(acc, w1p, H_,
                   (const ulonglong2*)&hbuf[rbase + 0][4 * kb],
                   (const ulonglong2*)&hbuf[rbase + 1][4 * kb],
                   (const ulonglong2*)&hbuf[rbase + 2][4 * kb],
                   (const ulonglong2*)&hbuf[rbase + 3][4 * kb], 32);
            float hs[4];
#pragma unroll
            for (int rr = 0; rr < 4; rr++) hs[rr] = hadd2(acc[rr]);
            if (!comb) {
#pragma unroll
                for (int rr = 0; rr < 4; rr++) PART(rbase + rr, j0) = hs[rr];
            }
            __syncthreads();
            if (comb) {
#pragma unroll
                for (int rr = 0; rr < 4; rr++) {
                    int r = rbase + rr;
                    float a = tanhf(b1j + hs[rr] + PART(r, j0));
                    a1buf[r][jg] = a;
                    sts_peer_f32(&a1buf[r][jg], peer, a);
                }
            }
        }
        cluster_sync_();

        // ---- stage 3: f = a1 @ w2^T + b2 ; euler ; h_ode ----
        {
            ull acc[4] = {0ull, 0ull, 0ull, 0ull};
            gemm4p(acc, w2p, H_,
                   (const ulonglong2*)&a1buf[rbase + 0][4 * kb],
                   (const ulonglong2*)&a1buf[rbase + 1][4 * kb],
                   (const ulonglong2*)&a1buf[rbase + 2][4 * kb],
                   (const ulonglong2*)&a1buf[rbase + 3][4 * kb], 32);
            float hs[4];
#pragma unroll
            for (int rr = 0; rr < 4; rr++) hs[rr] = hadd2(acc[rr]);
            if (!comb) {
#pragma unroll
                for (int rr = 0; rr < 4; rr++) PART(rbase + rr, j0) = hs[rr];
            }
            __syncthreads();
            if (comb) {
                const float dtv = g_dt[t];
#pragma unroll
                for (int rr = 0; rr < 4; rr++) {
                    int r = rbase + rr;
                    float f = b2j + hs[rr] + PART(r, j0);
                    float he = hcur[rr] + dtv * f;
                    float ho = (seen[rr] > 0.0f) ? he : hcur[rr];
                    hode[rr] = ho;
                    odebuf[r][jg] = ho;
                    sts_peer_f32(&odebuf[r][jg], peer, ho);
                }
            }
        }
        cluster_sync_();

        // ---- stage 4: gates, fully fused k-loops ----
        {
            ull aR[4] = {0ull, 0ull, 0ull, 0ull};
            ull aZ[4] = {0ull, 0ull, 0ull, 0ull};
            ull aN[4] = {0ull, 0ull, 0ull, 0ull};
            ull aI[4] = {0ull, 0ull, 0ull, 0ull};

            // recurrent part: r,z,n over odebuf (one LDS per quad per row)
            {
                const ulonglong2* v0 = (const ulonglong2*)&odebuf[rbase + 0][4 * kb];
                const ulonglong2* v1 = (const ulonglong2*)&odebuf[rbase + 1][4 * kb];
                const ulonglong2* v2 = (const ulonglong2*)&odebuf[rbase + 2][4 * kb];
                const ulonglong2* v3 = (const ulonglong2*)&odebuf[rbase + 3][4 * kb];
#pragma unroll 4
                for (int kk = 0; kk < 32; kk++) {
                    ulonglong2 wr = whp[kk * (3 * H_)];
                    ulonglong2 wz = whp[kk * (3 * H_) + H_];
                    ulonglong2 wn = whp[kk * (3 * H_) + 2 * H_];
                    ulonglong2 a0 = v0[kk], a1v = v1[kk], a2 = v2[kk], a3 = v3[kk];
                    aR[0] = ffma2(wr.x, a0.x, aR[0]); aR[0] = ffma2(wr.y, a0.y, aR[0]);
                    aZ[0] = ffma2(wz.x, a0.x, aZ[0]); aZ[0] = ffma2(wz.y, a0.y, aZ[0]);
                    aN[0] = ffma2(wn.x, a0.x, aN[0]); aN[0] = ffma2(wn.y, a0.y, aN[0]);
                    aR[1] = ffma2(wr.x, a1v.x, aR[1]); aR[1] = ffma2(wr.y, a1v.y, aR[1]);
                    aZ[1] = ffma2(wz.x, a1v.x, aZ[1]); aZ[1] = ffma2(wz.y, a1v.y, aZ[1]);
                    aN[1] = ffma2(wn.x, a1v.x, aN[1]); aN[1] = ffma2(wn.y, a1v.y, aN[1]);
                    aR[2] = ffma2(wr.x, a2.x, aR[2]); aR[2] = ffma2(wr.y, a2.y, aR[2]);
                    aZ[2] = ffma2(wz.x, a2.x, aZ[2]); aZ[2] = ffma2(wz.y, a2.y, aZ[2]);
                    aN[2] = ffma2(wn.x, a2.x, aN[2]); aN[2] = ffma2(wn.y, a2.y, aN[2]);
                    aR[3] = ffma2(wr.x, a3.x, aR[3]); aR[3] = ffma2(wr.y, a3.y, aR[3]);
                    aZ[3] = ffma2(wz.x, a3.x, aZ[3]); aZ[3] = ffma2(wz.y, a3.y, aZ[3]);
                    aN[3] = ffma2(wn.x, a3.x, aN[3]); aN[3] = ffma2(wn.y, a3.y, aN[3]);
                }
            }
            // input part: r,z,i over xbuf
            {
                const ulonglong2* v0 = (const ulonglong2*)&xbuf[rbase + 0][4 * kbx];
                const ulonglong2* v1 = (const ulonglong2*)&xbuf[rbase + 1][4 * kbx];
                const ulonglong2* v2 = (const ulonglong2*)&xbuf[rbase + 2][4 * kbx];
                const ulonglong2* v3 = (const ulonglong2*)&xbuf[rbase + 3][4 * kbx];
#pragma unroll
                for (int kk = 0; kk < 8; kk++) {
                    ulonglong2 wr = wip[kk * (3 * H_)];
                    ulonglong2 wz = wip[kk * (3 * H_) + H_];
                    ulonglong2 wn = wip[kk * (3 * H_) + 2 * H_];
                    ulonglong2 a0 = v0[kk], a1v = v1[kk], a2 = v2[kk], a3 = v3[kk];
                    aR[0] = ffma2(wr.x, a0.x, aR[0]); aR[0] = ffma2(wr.y, a0.y, aR[0]);
                    aZ[0] = ffma2(wz.x, a0.x, aZ[0]); aZ[0] = ffma2(wz.y, a0.y, aZ[0]);
                    aI[0] = ffma2(wn.x, a0.x, aI[0]); aI[0] = ffma2(wn.y, a0.y, aI[0]);
                    aR[1] = ffma2(wr.x, a1v.x, aR[1]); aR[1] = ffma2(wr.y, a1v.y, aR[1]);
                    aZ[1] = ffma2(wz.x, a1v.x, aZ[1]); aZ[1] = ffma2(wz.y, a1v.y, aZ[1]);
                    aI[1] = ffma2(wn.x, a1v.x, aI[1]); aI[1] = ffma2(wn.y, a1v.y, aI[1]);
                    aR[2] = ffma2(wr.x, a2.x, aR[2]); aR[2] = ffma2(wr.y, a2.y, aR[2]);
                    aZ[2] = ffma2(wz.x, a2.x, aZ[2]); aZ[2] = ffma2(wz.y, a2.y, aZ[2]);
                    aI[2] = ffma2(wn.x, a2.x, aI[2]); aI[2] = ffma2(wn.y, a2.y, aI[2]);
                    aR[3] = ffma2(wr.x, a3.x, aR[3]); aR[3] = ffma2(wr.y, a3.y, aR[3]);
                    aZ[3] = ffma2(wz.x, a3.x, aZ[3]); aZ[3] = ffma2(wz.y, a3.y, aZ[3]);
                    aI[3] = ffma2(wn.x, a3.x, aI[3]); aI[3] = ffma2(wn.y, a3.y, aI[3]);
                }
            }

            float hsR[4], hsZ[4], hsN[4], hsI[4];
#pragma unroll
            for (int rr = 0; rr < 4; rr++) {
                hsR[rr] = hadd2(aR[rr]); hsZ[rr] = hadd2(aZ[rr]);
                hsN[rr] = hadd2(aN[rr]); hsI[rr] = hadd2(aI[rr]);
            }
            if (!comb) {
#pragma unroll
                for (int rr = 0; rr < 4; rr++) {
                    int r = rbase + rr;
                    PART(r, j0) = hsR[rr];
                    PART(8 + r, j0) = hsZ[rr];
                    PART(16 + r, j0) = hsN[rr];
                    PART(24 + r, j0) = hsI[rr];
                }
            }
            __syncthreads();
            if (comb) {
#pragma unroll
                for (int rr = 0; rr < 4; rr++) {
                    int r = rbase + rr;
                    float fr = brz_r + hsR[rr] + PART(r, j0);
                    float fz = brz_z + hsZ[rr] + PART(8 + r, j0);
                    float fn = bhn + hsN[rr] + PART(16 + r, j0);
                    float fi = bin_ + hsI[rr] + PART(24 + r, j0);
                    float rg = sigmoidf_(fr);
                    float zg = sigmoidf_(fz);
                    float ng = tanhf(fi + rg * fn);
                    float hrnn = (1.0f - zg) * ng + zg * hode[rr];
                    float m = smk[r];
                    float hn = (m > 0.5f) ? hrnn : hode[rr];
                    hcur[rr] = hn;
                    hlast[rr] = (m > 0.5f) ? hn : hlast[rr];
                    seen[rr] = fmaxf(seen[rr], m);
                    hbuf[r][jg] = hn;
                    sts_peer_f32(&hbuf[r][jg], peer, hn);
                }
            }
        }
        cluster_sync_();
    }

    // ---- final projection: out = h_last @ w_out^T + b_out ----
    if (comb) {
#pragma unroll
        for (int rr = 0; rr < 4; rr++) {
            int r = rbase + rr;
            hbuf[r][jg] = hlast[rr];
            sts_peer_f32(&hbuf[r][jg], peer, hlast[rr]);
        }
    }
    cluster_sync_();
    {
        ull acc[4] = {0ull, 0ull, 0ull, 0ull};
        gemm4p(acc, wop, H_,
               (const ulonglong2*)&hbuf[rbase + 0][4 * kb],
               (const ulonglong2*)&hbuf[rbase + 1][4 * kb],
               (const ulonglong2*)&hbuf[rbase + 2][4 * kb],
               (const ulonglong2*)&hbuf[rbase + 3][4 * kb], 32);
        float hs[4];
#pragma unroll
        for (int rr = 0; rr < 4; rr++) hs[rr] = hadd2(acc[rr]);
        if (!comb) {
#pragma unroll
            for (int rr = 0; rr < 4; rr++) PART(rbase + rr, j0) = hs[rr];
        }
        __syncthreads();
        if (comb) {
            const float bo = b_out[jg];
#pragma unroll
            for (int rr = 0; rr < 4; rr++) {
                int r = rbase + rr;
                out[(size_t)(row0 + r) * H_ + jg] = bo + hs[rr] + PART(r, j0);
            }
        }
    }
    cluster_sync_();
}

extern "C" void kernel_launch(void* const* d_in, const int* in_sizes, int n_in,
                              void* d_out, int out_size) {
    const float* x     = (const float*)d_in[0];
    const float* tps   = (const float*)d_in[1];
    const float* mask  = (const float*)d_in[2];
    const float* w_ih  = (const float*)d_in[3];
    const float* w_hh  = (const float*)d_in[4];
    const float* b_ih  = (const float*)d_in[5];
    const float* b_hh  = (const float*)d_in[6];
    const float* w1    = (const float*)d_in[7];
    const float* b1    = (const float*)d_in[8];
    const float* w2    = (const float*)d_in[9];
    const float* b2    = (const float*)d_in[10];
    const float* w_out = (const float*)d_in[11];
    const float* b_out = (const float*)d_in[12];
    float* out = (float*)d_out;

    pack_all_kernel<<<(PK_TOTAL + 255) / 256, 256>>>(w1, w2, w_hh, w_ih, w_out, tps);
    gruode_kernel<<<NCTA, THREADS>>>(x, mask, b_ih, b_hh, b1, b2, b_out, out);
}

// round 10
// speedup vs baseline: 1.3972x; 1.0811x over previous
#include <cuda_runtime.h>
#include <cstdint>

#define T_ 256
#define D_ 64
#define H_ 256
#define B_ 512
#define ROWSC 8          // batch rows per cluster
#define JH 128           // output columns per CTA
#define NCTA 128
#define THREADS 512      // (kq:2) | (j0:7)

#define VS 260           // vector row stride (floats), 16B aligned
#define XS 68
#define NSLOT 32

// dynamic smem layout (floats)
#define OFF_H    0
#define OFF_ODE  (OFF_H + ROWSC * VS)
#define OFF_A1   (OFF_ODE + ROWSC * VS)
#define OFF_X    (OFF_A1 + ROWSC * VS)
#define OFF_MK   (OFF_X + ROWSC * XS)
#define OFF_DT   (OFF_MK + 8)
#define OFF_PART (OFF_DT + T_)
#define SMEM_FLOATS (OFF_PART + 4 * NSLOT * JH)
#define SMEM_BYTES (SMEM_FLOATS * 4)

// packed: P[k4 * O + o] = float4{ W[o][4k4+0..3] }
__device__ float4 g_w1p[(H_ / 4) * H_];
__device__ float4 g_w2p[(H_ / 4) * H_];
__device__ float4 g_whhp[(H_ / 4) * (3 * H_)];
__device__ float4 g_wihp[(D_ / 4) * (3 * H_)];
__device__ float4 g_woutp[(H_ / 4) * H_];
__device__ float g_dt[T_];

#define N_W1 ((H_ / 4) * H_)
#define N_WHH ((H_ / 4) * (3 * H_))
#define N_WIH ((D_ / 4) * (3 * H_))
#define PK_TOTAL (3 * N_W1 + N_WHH + N_WIH)

__global__ void pack_all_kernel(const float* __restrict__ w1,
                                const float* __restrict__ w2,
                                const float* __restrict__ whh,
                                const float* __restrict__ wih,
                                const float* __restrict__ wout,
                                const float* __restrict__ tps) {
    int idx = blockIdx.x * blockDim.x + threadIdx.x;
    if (idx < T_) {
        g_dt[idx] = (idx == 0) ? (tps[0] - (tps[0] - 0.01f))
                               : (tps[idx] - tps[idx - 1]);
    }
    if (idx >= PK_TOTAL) return;
    const float* src; float4* dst; int O, K, local = idx;
    if (local < N_W1) { src = w1; dst = g_w1p; O = H_; K = H_; }
    else if ((local -= N_W1) < N_W1) { src = w2; dst = g_w2p; O = H_; K = H_; }
    else if ((local -= N_W1) < N_WHH) { src = whh; dst = g_whhp; O = 3 * H_; K = H_; }
    else if ((local -= N_WHH) < N_WIH) { src = wih; dst = g_wihp; O = 3 * H_; K = D_; }
    else { local -= N_WIH; src = wout; dst = g_woutp; O = H_; K = H_; }
    int k4 = local / O;
    int o = local % O;
    const float* s = src + (size_t)o * K + 4 * k4;
    dst[local] = make_float4(s[0], s[1], s[2], s[3]);
}

typedef unsigned long long ull;
__device__ __forceinline__ ull ffma2(ull a, ull b, ull c) {
    ull d; asm("fma.rn.f32x2 %0, %1, %2, %3;" : "=l"(d) : "l"(a), "l"(b), "l"(c)); return d;
}
__device__ __forceinline__ float hadd2(ull v) {
    float2 f; asm("mov.b64 {%0, %1}, %2;" : "=f"(f.x), "=f"(f.y) : "l"(v));
    return f.x + f.y;
}
__device__ __forceinline__ float sigmoidf_(float v) { return 1.0f / (1.0f + expf(-v)); }

__device__ __forceinline__ void sts_peer_f32(const void* laddr, uint32_t peer, float v) {
    uint32_t la = (uint32_t)__cvta_generic_to_shared(laddr), ra;
    asm("mapa.shared::cluster.u32 %0, %1, %2;" : "=r"(ra) : "r"(la), "r"(peer));
    asm volatile("st.shared::cluster.b32 [%0], %1;" :: "r"(ra), "r"(__float_as_uint(v)) : "memory");
}
__device__ __forceinline__ void cluster_sync_() {
    asm volatile("barrier.cluster.arrive.aligned;" ::: "memory");
    asm volatile("barrier.cluster.wait.aligned;" ::: "memory");
}

// 8-row GEMM chunk: acc[r] += W[jg][k-chunk] . v[r][k-chunk]
// wp pre-offset to (kq-chunk, col); vbase pre-offset to kq-chunk; addresses imm-indexed.
__device__ __forceinline__ void gemm8q(ull acc[8], const ulonglong2* __restrict__ wp, int wstep,
                                       const float* __restrict__ vbase, int nkk) {
#pragma unroll 4
    for (int kk = 0; kk < nkk; kk++) {
        ulonglong2 w = wp[kk * wstep];
#pragma unroll
        for (int r = 0; r < 8; r++) {
            ulonglong2 v = *reinterpret_cast<const ulonglong2*>(vbase + r * VS + 4 * kk);
            acc[r] = ffma2(w.x, v.x, acc[r]);
            acc[r] = ffma2(w.y, v.y, acc[r]);
        }
    }
}

#define PART4(kq_, slot_, j_) sm[OFF_PART + ((kq_) * NSLOT + (slot_)) * JH + (j_)]

__global__ void __launch_bounds__(THREADS, 1) __cluster_dims__(2, 1, 1)
gruode_kernel(const float* __restrict__ x,
              const float* __restrict__ mask,
              const float* __restrict__ b_ih,
              const float* __restrict__ b_hh,
              const float* __restrict__ b1,
              const float* __restrict__ b2,
              const float* __restrict__ b_out,
              float* __restrict__ out) {
    extern __shared__ float sm[];
    float* hbuf = sm + OFF_H;
    float* odebuf = sm + OFF_ODE;
    float* a1buf = sm + OFF_A1;
    float* xbuf = sm + OFF_X;
    float* smk = sm + OFF_MK;
    float* sdt = sm + OFF_DT;

    const ulonglong2* w1u = reinterpret_cast<const ulonglong2*>(g_w1p);
    const ulonglong2* w2u = reinterpret_cast<const ulonglong2*>(g_w2p);
    const ulonglong2* whhu = reinterpret_cast<const ulonglong2*>(g_whhp);
    const ulonglong2* wihu = reinterpret_cast<const ulonglong2*>(g_wihp);
    const ulonglong2* woutu = reinterpret_cast<const ulonglong2*>(g_woutp);

    const int tid = threadIdx.x;
    const int j0 = tid & (JH - 1);
    const int kq = tid >> 7;           // 0..3 : k-quarter AND row-ownership group
    uint32_t rank;
    asm("mov.u32 %0, %%cluster_ctarank;" : "=r"(rank));
    const uint32_t peer = rank ^ 1u;
    const int jg = (int)rank * JH + j0;
    const int row0 = (blockIdx.x >> 1) * ROWSC;
    const int ro0 = 2 * kq, ro1 = 2 * kq + 1;   // owned rows

    for (int idx = tid; idx < ROWSC * VS; idx += THREADS) hbuf[idx] = 0.0f;
    for (int i = tid; i < T_; i += THREADS) sdt[i] = g_dt[i];

    // per-thread recurrent state for owned rows
    float hc0 = 0.0f, hc1 = 0.0f, hl0 = 0.0f, hl1 = 0.0f;
    float se0 = 0.0f, se1 = 0.0f, ho0 = 0.0f, ho1 = 0.0f;

    const float b1j = b1[jg];
    const float b2j = b2[jg];
    const float brz_r = b_ih[jg] + b_hh[jg];
    const float brz_z = b_ih[H_ + jg] + b_hh[H_ + jg];
    const float bin_ = b_ih[2 * H_ + jg];
    const float bhn = b_hh[2 * H_ + jg];

    // weight bases pre-offset by (k-quarter, column)
    const ulonglong2* w1p = w1u + (kq * 16) * H_ + jg;
    const ulonglong2* w2p = w2u + (kq * 16) * H_ + jg;
    const ulonglong2* whp = whhu + (kq * 16) * (3 * H_) + jg;   // +H_ => z, +2H_ => n
    const ulonglong2* wip = wihu + (kq * 4) * (3 * H_) + jg;
    const ulonglong2* wop = woutu + (kq * 16) * H_ + jg;
    const float* vh = hbuf + 4 * (kq * 16);
    const float* vode = odebuf + 4 * (kq * 16);
    const float* va1 = a1buf + 4 * (kq * 16);
    const float* vx = xbuf + 4 * (kq * 4);

    cluster_sync_();

    for (int t = 0; t < T_; t++) {
        // ---- stage 1: x_t + mask ----
        {
            int r = tid >> 6, c = tid & 63;
            xbuf[r * XS + c] = x[((size_t)(row0 + r) * T_ + t) * D_ + c];
        }
        if (tid < ROWSC) smk[tid] = mask[(size_t)(row0 + tid) * T_ + t];

        // ---- stage 2: a1 = tanh(h @ w1^T + b1) ----
        {
            ull acc[8] = {0ull, 0ull, 0ull, 0ull, 0ull, 0ull, 0ull, 0ull};
            gemm8q(acc, w1p, H_, vh, 16);
#pragma unroll
            for (int r = 0; r < 8; r++) PART4(kq, r, j0) = hadd2(acc[r]);
            __syncthreads();
            {
                float s0 = b1j + PART4(0, ro0, j0) + PART4(1, ro0, j0) + PART4(2, ro0, j0) + PART4(3, ro0, j0);
                float s1 = b1j + PART4(0, ro1, j0) + PART4(1, ro1, j0) + PART4(2, ro1, j0) + PART4(3, ro1, j0);
                float a0 = tanhf(s0), a1v = tanhf(s1);
                a1buf[ro0 * VS + jg] = a0;
                a1buf[ro1 * VS + jg] = a1v;
                sts_peer_f32(&a1buf[ro0 * VS + jg], peer, a0);
                sts_peer_f32(&a1buf[ro1 * VS + jg], peer, a1v);
            }
        }
        cluster_sync_();

        // ---- stage 3: f = a1 @ w2^T + b2 ; euler ; h_ode ----
        {
            ull acc[8] = {0ull, 0ull, 0ull, 0ull, 0ull, 0ull, 0ull, 0ull};
            gemm8q(acc, w2p, H_, va1, 16);
#pragma unroll
            for (int r = 0; r < 8; r++) PART4(kq, r, j0) = hadd2(acc[r]);
            __syncthreads();
            {
                const float dtv = sdt[t];
                float f0 = b2j + PART4(0, ro0, j0) + PART4(1, ro0, j0) + PART4(2, ro0, j0) + PART4(3, ro0, j0);
                float f1 = b2j + PART4(0, ro1, j0) + PART4(1, ro1, j0) + PART4(2, ro1, j0) + PART4(3, ro1, j0);
                float he0 = hc0 + dtv * f0;
                float he1 = hc1 + dtv * f1;
                ho0 = (se0 > 0.0f) ? he0 : hc0;
                ho1 = (se1 > 0.0f) ? he1 : hc1;
                odebuf[ro0 * VS + jg] = ho0;
                odebuf[ro1 * VS + jg] = ho1;
                sts_peer_f32(&odebuf[ro0 * VS + jg], peer, ho0);
                sts_peer_f32(&odebuf[ro1 * VS + jg], peer, ho1);
            }
        }
        cluster_sync_();

        // ---- stage 4: gates ----
        {
            ull aR[8] = {0ull, 0ull, 0ull, 0ull, 0ull, 0ull, 0ull, 0ull};
            ull aZ[8] = {0ull, 0ull, 0ull, 0ull, 0ull, 0ull, 0ull, 0ull};
            // pass A: r,z,n over odebuf (each quad LDS'd once)
            {
                ull aN[8] = {0ull, 0ull, 0ull, 0ull, 0ull, 0ull, 0ull, 0ull};
#pragma unroll 4
                for (int kk = 0; kk < 16; kk++) {
                    ulonglong2 wr = whp[kk * (3 * H_)];
                    ulonglong2 wz = whp[kk * (3 * H_) + H_];
                    ulonglong2 wn = whp[kk * (3 * H_) + 2 * H_];
#pragma unroll
                    for (int r = 0; r < 8; r++) {
                        ulonglong2 v = *reinterpret_cast<const ulonglong2*>(vode + r * VS + 4 * kk);
                        aR[r] = ffma2(wr.x, v.x, aR[r]); aR[r] = ffma2(wr.y, v.y, aR[r]);
                        aZ[r] = ffma2(wz.x, v.x, aZ[r]); aZ[r] = ffma2(wz.y, v.y, aZ[r]);
                        aN[r] = ffma2(wn.x, v.x, aN[r]); aN[r] = ffma2(wn.y, v.y, aN[r]);
                    }
                }
#pragma unroll
                for (int r = 0; r < 8; r++) PART4(kq, 16 + r, j0) = hadd2(aN[r]);
            }
            // pass B: r,z continue; i over xbuf
            {
                ull aI[8] = {0ull, 0ull, 0ull, 0ull, 0ull, 0ull, 0ull, 0ull};
#pragma unroll
                for (int kk = 0; kk < 4; kk++) {
                    ulonglong2 wr = wip[kk * (3 * H_)];
                    ulonglong2 wz = wip[kk * (3 * H_) + H_];
                    ulonglong2 wi = wip[kk * (3 * H_) + 2 * H_];
#pragma unroll
                    for (int r = 0; r < 8; r++) {
                        ulonglong2 v = *reinterpret_cast<const ulonglong2*>(vx + r * XS + 4 * kk);
                        aR[r] = ffma2(wr.x, v.x, aR[r]); aR[r] = ffma2(wr.y, v.y, aR[r]);
                        aZ[r] = ffma2(wz.x, v.x, aZ[r]); aZ[r] = ffma2(wz.y, v.y, aZ[r]);
                        aI[r] = ffma2(wi.x, v.x, aI[r]); aI[r] = ffma2(wi.y, v.y, aI[r]);
                    }
                }
#pragma unroll
                for (int r = 0; r < 8; r++) {
                    PART4(kq, r, j0) = hadd2(aR[r]);
                    PART4(kq, 8 + r, j0) = hadd2(aZ[r]);
                    PART4(kq, 24 + r, j0) = hadd2(aI[r]);
                }
            }
            __syncthreads();
            // reduce own 2 rows, gates, h update
            {
#pragma unroll
                for (int q = 0; q < 2; q++) {
                    int r = (q == 0) ? ro0 : ro1;
                    float hoq = (q == 0) ? ho0 : ho1;
                    float fr = brz_r + PART4(0, r, j0) + PART4(1, r, j0) + PART4(2, r, j0) + PART4(3, r, j0);
                    float fz = brz_z + PART4(0, 8 + r, j0) + PART4(1, 8 + r, j0) + PART4(2, 8 + r, j0) + PART4(3, 8 + r, j0);
                    float fn = bhn + PART4(0, 16 + r, j0) + PART4(1, 16 + r, j0) + PART4(2, 16 + r, j0) + PART4(3, 16 + r, j0);
                    float fi = bin_ + PART4(0, 24 + r, j0) + PART4(1, 24 + r, j0) + PART4(2, 24 + r, j0) + PART4(3, 24 + r, j0);
                    float rg = sigmoidf_(fr);
                    float zg = sigmoidf_(fz);
                    float ng = tanhf(fi + rg * fn);
                    float hrnn = (1.0f - zg) * ng + zg * hoq;
                    float m = smk[r];
                    float hn = (m > 0.5f) ? hrnn : hoq;
                    if (q == 0) {
                        hc0 = hn; hl0 = (m > 0.5f) ? hn : hl0; se0 = fmaxf(se0, m);
                    } else {
                        hc1 = hn; hl1 = (m > 0.5f) ? hn : hl1; se1 = fmaxf(se1, m);
                    }
                    hbuf[r * VS + jg] = hn;
                    sts_peer_f32(&hbuf[r * VS + jg], peer, hn);
                }
            }
        }
        cluster_sync_();
    }

    // ---- final projection: out = h_last @ w_out^T + b_out ----
    hbuf[ro0 * VS + jg] = hl0;
    hbuf[ro1 * VS + jg] = hl1;
    sts_peer_f32(&hbuf[ro0 * VS + jg], peer, hl0);
    sts_peer_f32(&hbuf[ro1 * VS + jg], peer, hl1);
    cluster_sync_();
    {
        ull acc[8] = {0ull, 0ull, 0ull, 0ull, 0ull, 0ull, 0ull, 0ull};
        gemm8q(acc, wop, H_, vh, 16);
#pragma unroll
        for (int r = 0; r < 8; r++) PART4(kq, r, j0) = hadd2(acc[r]);
        __syncthreads();
        {
            const float bo = b_out[jg];
            float s0 = bo + PART4(0, ro0, j0) + PART4(1, ro0, j0) + PART4(2, ro0, j0) + PART4(3, ro0, j0);
            float s1 = bo + PART4(0, ro1, j0) + PART4(1, ro1, j0) + PART4(2, ro1, j0) + PART4(3, ro1, j0);
            out[(size_t)(row0 + ro0) * H_ + jg] = s0;
            out[(size_t)(row0 + ro1) * H_ + jg] = s1;
        }
    }
    cluster_sync_();
}

extern "C" void kernel_launch(void* const* d_in, const int* in_sizes, int n_in,
                              void* d_out, int out_size) {
    const float* x     = (const float*)d_in[0];
    const float* tps   = (const float*)d_in[1];
    const float* mask  = (const float*)d_in[2];
    const float* w_ih  = (const float*)d_in[3];
    const float* w_hh  = (const float*)d_in[4];
    const float* b_ih  = (const float*)d_in[5];
    const float* b_hh  = (const float*)d_in[6];
    const float* w1    = (const float*)d_in[7];
    const float* b1    = (const float*)d_in[8];
    const float* w2    = (const float*)d_in[9];
    const float* b2    = (const float*)d_in[10];
    const float* w_out = (const float*)d_in[11];
    const float* b_out = (const float*)d_in[12];
    float* out = (float*)d_out;

    static bool attr_set = false;
    if (!attr_set) {
        cudaFuncSetAttribute(gruode_kernel,
                             cudaFuncAttributeMaxDynamicSharedMemorySize, SMEM_BYTES);
        attr_set = true;
    }

    pack_all_kernel<<<(PK_TOTAL + 255) / 256, 256>>>(w1, w2, w_hh, w_ih, w_out, tps);
    gruode_kernel<<<NCTA, THREADS, SMEM_BYTES>>>(x, mask, b_ih, b_hh, b1, b2, b_out, out);
}